// round 8
// baseline (speedup 1.0000x reference)
#include <cuda_runtime.h>

// ---------------- problem constants ----------------
#define HW        512
#define PLANES    48          // 16 batch * 3 channels
#define NPIX      12582912.0  // 48*512*512
#define TW        64
#define TH        32
#define SW        74          // TW + 10
#define SH        42          // TH + 10
#define S2STR     76          // row stride in 8-byte (float2) units
#define NTHREADS  320
#define NBLOCKS   6144        // 8*16*48

#define C1F 0.0001f
#define C2F 0.0009f

typedef unsigned long long u64;

// Gaussian(sigma=1.5) centered at 5.5, normalized (sum = 0.99999982).
// Empirically validated (rel_err 7.9e-5); tap precision is load-bearing
// (a -3.2e-4 tap-scale error amplifies ~500x through the C2=9e-4 term).
__device__ constexpr float GW[11] = {
    0.00032030f, 0.00295566f, 0.01748770f, 0.06634250f, 0.16137290f,
    0.25168100f, 0.25168100f, 0.16137290f, 0.06634250f, 0.01748770f,
    0.00295566f
};

__device__ double g_part[NBLOCKS];
__device__ unsigned int g_count = 0;   // self-resetting ticket (atomicInc wraps)

// ---- packed f32x2 helpers (Blackwell FFMA2/FMUL2; PTX-only, ptxas won't fuse) ----
#define FMA_F32X2(d, a, b, c) \
    asm("fma.rn.f32x2 %0, %1, %2, %3;" : "=l"(d) : "l"(a), "l"(b), "l"(c))
#define MUL_F32X2(d, a, b) \
    asm("mul.rn.f32x2 %0, %1, %2;" : "=l"(d) : "l"(a), "l"(b))

__device__ __forceinline__ u64 pack2(float lo, float hi) {
    return ((u64)__float_as_uint(hi) << 32) | (u64)__float_as_uint(lo);
}
__device__ __forceinline__ float lo2(u64 v) { return __uint_as_float((unsigned)v); }
__device__ __forceinline__ float hi2(u64 v) { return __uint_as_float((unsigned)(v >> 32)); }

// FMA-only reciprocal: magic seed + 2 Newton steps (err ~1.4e-6, << budget).
// Avoids MUFU.RCP (rt_SMSP=8 -> chip-wide floor at 12.6M divides).
__device__ __forceinline__ float fast_rcp(float d) {
    float r = __int_as_float(0x7EF311C3 - __float_as_int(d));
#pragma unroll
    for (int it = 0; it < 2; ++it) {
        float t = fmaf(-d, r, 1.0f);
        r = fmaf(r, t, r);
    }
    return r;
}

__global__ void __launch_bounds__(NTHREADS, 2)
ssim_main_kernel(const float* __restrict__ img1, const float* __restrict__ img2,
                 float* __restrict__ out) {
    // smem layout (8-byte words unless noted):
    //   s_ab  : SH*S2STR  u64   (a,b) interleaved input halo      25,536 B
    //   s_m01 : TH*S2STR  u64   packed (conv_a, conv_b)           19,456 B
    //   s_m23 : TH*S2STR  u64   packed (conv_a2, conv_b2)         19,456 B
    //   s_m4  : TH*S2STR  float conv_ab                            9,728 B
    extern __shared__ u64 smem8[];
    u64*   s_ab  = smem8;
    u64*   s_m01 = s_ab  + SH * S2STR;
    u64*   s_m23 = s_m01 + TH * S2STR;
    float* s_m4  = (float*)(s_m23 + TH * S2STR);

    const int tid   = threadIdx.x;
    const int plane = blockIdx.z;
    const int x0    = blockIdx.x * TW;
    const int y0    = blockIdx.y * TH;

    const float* __restrict__ p1 = img1 + (size_t)plane * HW * HW;
    const float* __restrict__ p2 = img2 + (size_t)plane * HW * HW;

    // packed weights (hoisted to 11 u64 regs; FFMA2 needs register operands)
    u64 w2[11];
#pragma unroll
    for (int i = 0; i < 11; ++i) w2[i] = pack2(GW[i], GW[i]);

    // ---------- Phase 1: load halo, store interleaved (a,b) as one STS.64 ----
    if (tid < 296) {
        const int x  = tid % 74;
        const int r0 = tid / 74;
        const int gx = x0 - 5 + x;
        const bool xin = (unsigned)gx < (unsigned)HW;
#pragma unroll
        for (int rr = 0; rr < 11; ++rr) {
            const int r = r0 + rr * 4;
            if (r < SH) {
                const int gy = y0 - 5 + r;
                float a = 0.f, b = 0.f;
                if (xin && (unsigned)gy < (unsigned)HW) {
                    const int gi = gy * HW + gx;
                    a = p1[gi];
                    b = p2[gi];
                }
                s_ab[r * S2STR + x] = pack2(a, b);
            }
        }
    }
    __syncthreads();

    // ---------- Phase 2: vertical 11-tap conv, packed pairs ----------
    // per tap: 1 LDS.64 + 1 FMUL2 + 1 FMUL, per output: 2 FFMA2 + 1 FFMA
    // (3 issue slots for 5 quantity-lanes vs 5 scalar).
    if (tid < 296) {                 // 74 columns * 4 row-groups of 8
        const int x  = tid % 74;
        const int yb = (tid / 74) * 8;

        u64 a01[8], a23[8];
        float a4[8];
#pragma unroll
        for (int r = 0; r < 8; ++r) { a01[r] = 0ull; a23[r] = 0ull; a4[r] = 0.f; }
#pragma unroll
        for (int jj = 0; jj < 18; ++jj) {
            const u64 p01 = s_ab[(yb + jj) * S2STR + x];
            u64 p23;
            MUL_F32X2(p23, p01, p01);                  // (a*a, b*b)
            const float vab = lo2(p01) * hi2(p01);     // a*b
#pragma unroll
            for (int r = 0; r < 8; ++r) {
                const int j = jj - r;
                if (0 <= j && j < 11) {
                    FMA_F32X2(a01[r], p01, w2[j], a01[r]);
                    FMA_F32X2(a23[r], p23, w2[j], a23[r]);
                    a4[r] = fmaf(GW[j], vab, a4[r]);
                }
            }
        }
#pragma unroll
        for (int r = 0; r < 8; ++r) {
            s_m01[(yb + r) * S2STR + x] = a01[r];
            s_m23[(yb + r) * S2STR + x] = a23[r];
            s_m4 [(yb + r) * S2STR + x] = a4[r];
        }
    }
    __syncthreads();

    // ---------- Phase 3: horizontal 11-tap conv (packed) + SSIM ----------
    float lsum = 0.f;
    if (tid < 256) {                  // 32 rows * 8 column-groups of 8
        const int y  = tid >> 3;
        const int xb = (tid & 7) * 8;

        u64 o01[8], o23[8];
        float o4[8];

        { // pair (q0,q1)
            u64 m[18];
#pragma unroll
            for (int i = 0; i < 18; ++i) m[i] = s_m01[y * S2STR + xb + i];
#pragma unroll
            for (int r = 0; r < 8; ++r) {
                u64 s = 0ull;
#pragma unroll
                for (int i = 0; i < 11; ++i) FMA_F32X2(s, m[r + i], w2[i], s);
                o01[r] = s;
            }
        }
        { // pair (q2,q3)
            u64 m[18];
#pragma unroll
            for (int i = 0; i < 18; ++i) m[i] = s_m23[y * S2STR + xb + i];
#pragma unroll
            for (int r = 0; r < 8; ++r) {
                u64 s = 0ull;
#pragma unroll
                for (int i = 0; i < 11; ++i) FMA_F32X2(s, m[r + i], w2[i], s);
                o23[r] = s;
            }
        }
        { // q4 scalar (FFMA-imm form)
            float m[18];
#pragma unroll
            for (int i = 0; i < 18; ++i) m[i] = s_m4[y * S2STR + xb + i];
#pragma unroll
            for (int r = 0; r < 8; ++r) {
                float s = GW[0] * m[r];
#pragma unroll
                for (int i = 1; i < 11; ++i) s = fmaf(GW[i], m[r + i], s);
                o4[r] = s;
            }
        }
#pragma unroll
        for (int r = 0; r < 8; ++r) {
            const float mu1 = lo2(o01[r]), mu2 = hi2(o01[r]);
            const float e11 = lo2(o23[r]), e22 = hi2(o23[r]);
            const float e12 = o4[r];
            const float m11 = mu1 * mu1;
            const float m22 = mu2 * mu2;
            const float m12 = mu1 * mu2;
            const float s1  = e11 - m11;
            const float s2  = e22 - m22;
            const float s12 = e12 - m12;
            const float num = fmaf(2.f, m12, C1F) * fmaf(2.f, s12, C2F);
            const float den = (m11 + m22 + C1F) * (s1 + s2 + C2F);
            lsum = fmaf(num, fast_rcp(den), lsum);
        }
    }

    // ---------- In-block reduction ----------
#pragma unroll
    for (int off = 16; off > 0; off >>= 1)
        lsum += __shfl_down_sync(0xffffffffu, lsum, off);

    __shared__ float  warp_sums[NTHREADS / 32];
    __shared__ unsigned s_last;
    const int wid  = tid >> 5;
    const int lane = tid & 31;
    if (lane == 0) warp_sums[wid] = lsum;
    __syncthreads();

    // ---------- Last-block-done global reduction (no 2nd kernel) ----------
    if (tid == 0) {
        float s = 0.f;
#pragma unroll
        for (int w = 0; w < NTHREADS / 32; ++w) s += warp_sums[w];
        const int bid = (blockIdx.z * gridDim.y + blockIdx.y) * gridDim.x + blockIdx.x;
        g_part[bid] = (double)s;
        __threadfence();
        const unsigned ticket = atomicInc(&g_count, NBLOCKS - 1);
        s_last = (ticket == NBLOCKS - 1) ? 1u : 0u;
    }
    __syncthreads();

    if (s_last) {
        __threadfence();
        double d = 0.0;
        for (int i = tid; i < NBLOCKS; i += NTHREADS) d += g_part[i];
#pragma unroll
        for (int off = 16; off > 0; off >>= 1)
            d += __shfl_down_sync(0xffffffffu, d, off);
        __shared__ double wsum[NTHREADS / 32];
        if (lane == 0) wsum[wid] = d;
        __syncthreads();
        if (tid == 0) {
            double t = 0.0;
#pragma unroll
            for (int w = 0; w < NTHREADS / 32; ++w) t += wsum[w];
            out[0] = (float)(t * (1.0 / NPIX));
        }
    }
}

extern "C" void kernel_launch(void* const* d_in, const int* in_sizes, int n_in,
                              void* d_out, int out_size) {
    const float* img1 = (const float*)d_in[0];
    const float* img2 = (const float*)d_in[1];
    float* out = (float*)d_out;

    // 25,536 + 19,456 + 19,456 + 9,728 = 74,176 B
    const int smem_bytes = (SH * S2STR + 2 * TH * S2STR) * 8 + TH * S2STR * 4;
    cudaFuncSetAttribute(ssim_main_kernel,
                         cudaFuncAttributeMaxDynamicSharedMemorySize, smem_bytes);

    dim3 grid(HW / TW, HW / TH, PLANES);   // 8 x 16 x 48
    ssim_main_kernel<<<grid, NTHREADS, smem_bytes>>>(img1, img2, out);
}

// round 9
// speedup vs baseline: 1.0594x; 1.0594x over previous
#include <cuda_runtime.h>

// ---------------- problem constants ----------------
#define HW        512
#define PLANES    48          // 16 batch * 3 channels
#define NPIX      12582912.0  // 48*512*512
#define TW        64
#define TH        32
#define SW        74          // TW + 10
#define SH        42          // TH + 10
#define SSTR      76          // padded smem row stride (floats)
#define NTHREADS  320
#define NBLOCKS   6144u       // 8*16*48

#define C1F 0.0001f
#define C2F 0.0009f

// Gaussian(sigma=1.5) centered at 5.5, normalized (sum = 0.99999982).
// Empirically validated (rel_err ~7.7e-5); tap precision is load-bearing
// (a -3.2e-4 tap-scale error amplifies ~500x through the C2=9e-4 term).
// __device__ constexpr + literal indices -> FFMA immediates (rt_SMSP=1, which
// R8 proved matches packed FFMA2 per-lane throughput -- scalar imm is optimal).
__device__ constexpr float GW[11] = {
    0.00032030f, 0.00295566f, 0.01748770f, 0.06634250f, 0.16137290f,
    0.25168100f, 0.25168100f, 0.16137290f, 0.06634250f, 0.01748770f,
    0.00295566f
};

__device__ float g_part[NBLOCKS];
__device__ unsigned int g_count = 0;   // self-resetting ticket (inc wraps at NBLOCKS-1)

// FMA-only reciprocal: magic seed + 2 Newton steps (err ~1.4e-6, << budget).
// Avoids MUFU.RCP (rt_SMSP=8 -> chip-wide floor at 12.6M divides).
__device__ __forceinline__ float fast_rcp(float d) {
    float r = __int_as_float(0x7EF311C3 - __float_as_int(d));
#pragma unroll
    for (int it = 0; it < 2; ++it) {
        float t = fmaf(-d, r, 1.0f);
        r = fmaf(r, t, r);
    }
    return r;
}

#define SIN1(r, c)    s_in1[(r) * SSTR + (c)]
#define SIN2(r, c)    s_in2[(r) * SSTR + (c)]
#define SMID(q, r, c) s_mid[((q) * TH + (r)) * SSTR + (c)]

__global__ void __launch_bounds__(NTHREADS, 2)
ssim_main_kernel(const float* __restrict__ img1, const float* __restrict__ img2,
                 float* __restrict__ out) {
    extern __shared__ float smem[];
    float* s_in1 = smem;                         // SH * SSTR
    float* s_in2 = smem + SH * SSTR;             // SH * SSTR
    float* s_mid = smem + 2 * SH * SSTR;         // 5 * TH * SSTR

    const int tid   = threadIdx.x;
    const int plane = blockIdx.z;
    const int x0    = blockIdx.x * TW;
    const int y0    = blockIdx.y * TH;

    const float* __restrict__ p1 = img1 + (size_t)plane * HW * HW;
    const float* __restrict__ p2 = img2 + (size_t)plane * HW * HW;

    // ---------- Phase 1: load halo tiles (zero-padded borders) — R3 form ----
#pragma unroll
    for (int ii = 0; ii < (SH * SW + NTHREADS - 1) / NTHREADS; ++ii) {
        const int i = tid + ii * NTHREADS;
        if (i < SH * SW) {
            const int r  = i / SW;
            const int c  = i - r * SW;
            const int gy = y0 - 5 + r;
            const int gx = x0 - 5 + c;
            float a = 0.f, b = 0.f;
            if ((unsigned)gy < (unsigned)HW && (unsigned)gx < (unsigned)HW) {
                const int gi = gy * HW + gx;
                a = p1[gi];
                b = p2[gi];
            }
            SIN1(r, c) = a;
            SIN2(r, c) = b;
        }
    }
    __syncthreads();

    // ---------- Phase 2: vertical 11-tap conv, single sweep, 5 quantities ----
    if (tid < 296) {                 // 74 columns * 4 row-groups of 8
        const int x  = tid % 74;
        const int yb = (tid / 74) * 8;

        float a0[8], a1[8], a2[8], a3[8], a4[8];
#pragma unroll
        for (int r = 0; r < 8; ++r) {
            a0[r] = 0.f; a1[r] = 0.f; a2[r] = 0.f; a3[r] = 0.f; a4[r] = 0.f;
        }
#pragma unroll
        for (int jj = 0; jj < 18; ++jj) {
            const float va  = SIN1(yb + jj, x);
            const float vb  = SIN2(yb + jj, x);
            const float vaa = va * va;
            const float vbb = vb * vb;
            const float vab = va * vb;
#pragma unroll
            for (int r = 0; r < 8; ++r) {
                const int j = jj - r;
                if (0 <= j && j < 11) {
                    a0[r] = fmaf(GW[j], va,  a0[r]);
                    a1[r] = fmaf(GW[j], vb,  a1[r]);
                    a2[r] = fmaf(GW[j], vaa, a2[r]);
                    a3[r] = fmaf(GW[j], vbb, a3[r]);
                    a4[r] = fmaf(GW[j], vab, a4[r]);
                }
            }
        }
#pragma unroll
        for (int r = 0; r < 8; ++r) {
            SMID(0, yb + r, x) = a0[r];
            SMID(1, yb + r, x) = a1[r];
            SMID(2, yb + r, x) = a2[r];
            SMID(3, yb + r, x) = a3[r];
            SMID(4, yb + r, x) = a4[r];
        }
    }
    __syncthreads();

    // ---------- Phase 3: horizontal 11-tap conv + SSIM ----------
    float lsum = 0.f;
    if (tid < 256) {                  // 32 rows * 8 column-groups of 8
        const int y  = tid >> 3;
        const int xb = (tid & 7) * 8;

        float o[5][8];
#pragma unroll
        for (int q = 0; q < 5; ++q) {
            const float4* vp = reinterpret_cast<const float4*>(&SMID(q, y, xb));
            float m[20];
#pragma unroll
            for (int k = 0; k < 5; ++k) {
                const float4 v = vp[k];
                m[4 * k + 0] = v.x;
                m[4 * k + 1] = v.y;
                m[4 * k + 2] = v.z;
                m[4 * k + 3] = v.w;
            }
#pragma unroll
            for (int r = 0; r < 8; ++r) {
                float s = GW[0] * m[r];
#pragma unroll
                for (int i = 1; i < 11; ++i) s = fmaf(GW[i], m[r + i], s);
                o[q][r] = s;
            }
        }
#pragma unroll
        for (int r = 0; r < 8; ++r) {
            const float mu1 = o[0][r], mu2 = o[1][r];
            const float e11 = o[2][r], e22 = o[3][r], e12 = o[4][r];
            const float m11 = mu1 * mu1;
            const float m22 = mu2 * mu2;
            const float m12 = mu1 * mu2;
            const float s1  = e11 - m11;
            const float s2  = e22 - m22;
            const float s12 = e12 - m12;
            const float num = fmaf(2.f, m12, C1F) * fmaf(2.f, s12, C2F);
            const float den = (m11 + m22 + C1F) * (s1 + s2 + C2F);
            lsum = fmaf(num, fast_rcp(den), lsum);
        }
    }

    // ---------- In-block reduction ----------
#pragma unroll
    for (int off = 16; off > 0; off >>= 1)
        lsum += __shfl_down_sync(0xffffffffu, lsum, off);

    __shared__ float  warp_sums[NTHREADS / 32];
    __shared__ unsigned s_last;
    const int wid  = tid >> 5;
    const int lane = tid & 31;
    if (lane == 0) warp_sums[wid] = lsum;
    __syncthreads();

    // ---------- Fence-free last-block reduction ----------
    // NO __threadfence(): gpu-scope membar makes ptxas emit CCTL.IVALL (L1D
    // flush per block) — the prime suspect for the R3(94us)->R5(107us) main-
    // kernel regression. Ordering instead via one acq_rel atomic:
    //   release leg: orders the g_part store before the ticket becomes visible
    //   acquire leg: last block's tid0 sees all producers' g_part stores;
    //                bar.sync extends visibility to the whole CTA.
    if (tid == 0) {
        float s = 0.f;
#pragma unroll
        for (int w = 0; w < NTHREADS / 32; ++w) s += warp_sums[w];
        const int bid = (blockIdx.z * gridDim.y + blockIdx.y) * gridDim.x + blockIdx.x;
        g_part[bid] = s;
        unsigned ticket;
        asm volatile("atom.acq_rel.gpu.global.inc.u32 %0, [%1], %2;"
                     : "=r"(ticket)
                     : "l"(&g_count), "r"(NBLOCKS - 1u)
                     : "memory");
        s_last = (ticket == NBLOCKS - 1u) ? 1u : 0u;
    }
    __syncthreads();

    if (s_last) {
        double d = 0.0;
        for (int i = tid; i < (int)NBLOCKS; i += NTHREADS) d += (double)g_part[i];
#pragma unroll
        for (int off = 16; off > 0; off >>= 1)
            d += __shfl_down_sync(0xffffffffu, d, off);
        __shared__ double wsum[NTHREADS / 32];
        if (lane == 0) wsum[wid] = d;
        __syncthreads();
        if (tid == 0) {
            double t = 0.0;
#pragma unroll
            for (int w = 0; w < NTHREADS / 32; ++w) t += wsum[w];
            out[0] = (float)(t * (1.0 / NPIX));
        }
    }
}

extern "C" void kernel_launch(void* const* d_in, const int* in_sizes, int n_in,
                              void* d_out, int out_size) {
    const float* img1 = (const float*)d_in[0];
    const float* img2 = (const float*)d_in[1];
    float* out = (float*)d_out;

    const int smem_bytes = (2 * SH * SSTR + 5 * TH * SSTR) * (int)sizeof(float); // 74176
    cudaFuncSetAttribute(ssim_main_kernel,
                         cudaFuncAttributeMaxDynamicSharedMemorySize, smem_bytes);

    dim3 grid(HW / TW, HW / TH, PLANES);   // 8 x 16 x 48
    ssim_main_kernel<<<grid, NTHREADS, smem_bytes>>>(img1, img2, out);
}

// round 10
// speedup vs baseline: 1.2780x; 1.2063x over previous
#include <cuda_runtime.h>

// ---------------- problem constants ----------------
#define HW        512
#define PLANES    48          // 16 batch * 3 channels
#define NPIX      12582912.0  // 48*512*512
#define TW        64
#define TH        32
#define SW        74          // TW + 10
#define SH        42          // TH + 10
#define SSTR      76          // padded smem row stride (floats)
#define NTHREADS  320
#define NBLOCKS   6144u       // 8*16*48

#define C1F 0.0001f
#define C2F 0.0009f

// Gaussian(sigma=1.5) centered at 5.5, normalized (sum = 0.99999982).
// Tap precision is load-bearing (-3.2e-4 tap-scale error amplifies ~500x
// through the C2=9e-4 term). constexpr + literal indices -> FFMA-imm (rt=1).
__device__ constexpr float GW[11] = {
    0.00032030f, 0.00295566f, 0.01748770f, 0.06634250f, 0.16137290f,
    0.25168100f, 0.25168100f, 0.16137290f, 0.06634250f, 0.01748770f,
    0.00295566f
};

__device__ float g_part[NBLOCKS];
__device__ unsigned int g_count = 0;   // self-resetting ticket (inc wraps)

// FMA-only reciprocal: magic seed + 2 Newton steps (err ~1.4e-6, << budget).
// Avoids MUFU.RCP (rt_SMSP=8 -> chip-wide floor at 12.6M divides).
__device__ __forceinline__ float fast_rcp(float d) {
    float r = __int_as_float(0x7EF311C3 - __float_as_int(d));
#pragma unroll
    for (int it = 0; it < 2; ++it) {
        float t = fmaf(-d, r, 1.0f);
        r = fmaf(r, t, r);
    }
    return r;
}

// SSIM via sum/difference transform: only 4 convolutions needed.
//   s = a+b, d = a-b;  S=conv(s), D=conv(d), P=conv(s^2), Q=conv(d^2)
//   2*mu1mu2      = (S^2 - D^2)/2
//   mu1^2+mu2^2   = (S^2 + D^2)/2
//   E11+E22       = (P + Q)/2
//   2*sigma12     = ((P-Q) - (S^2-D^2))/2
//   sig1^2+sig2^2 = ((P+Q) - (S^2+D^2))/2

#define SS(r, c)      s_s[(r) * SSTR + (c)]
#define SD(r, c)      s_d[(r) * SSTR + (c)]
#define SMID(q, r, c) s_mid[((q) * TH + (r)) * SSTR + (c)]

__global__ void __launch_bounds__(NTHREADS, 2)
ssim_main_kernel(const float* __restrict__ img1, const float* __restrict__ img2,
                 float* __restrict__ out) {
    extern __shared__ float smem[];
    float* s_s   = smem;                         // SH * SSTR  (a+b)
    float* s_d   = smem + SH * SSTR;             // SH * SSTR  (a-b)
    float* s_mid = smem + 2 * SH * SSTR;         // 4 * TH * SSTR

    const int tid   = threadIdx.x;
    const int plane = blockIdx.z;
    const int x0    = blockIdx.x * TW;
    const int y0    = blockIdx.y * TH;

    const float* __restrict__ p1 = img1 + (size_t)plane * HW * HW;
    const float* __restrict__ p2 = img2 + (size_t)plane * HW * HW;

    // ---------- Phase 1: load halo, store (a+b, a-b) ----------
#pragma unroll
    for (int ii = 0; ii < (SH * SW + NTHREADS - 1) / NTHREADS; ++ii) {
        const int i = tid + ii * NTHREADS;
        if (i < SH * SW) {
            const int r  = i / SW;
            const int c  = i - r * SW;
            const int gy = y0 - 5 + r;
            const int gx = x0 - 5 + c;
            float a = 0.f, b = 0.f;
            if ((unsigned)gy < (unsigned)HW && (unsigned)gx < (unsigned)HW) {
                const int gi = gy * HW + gx;
                a = p1[gi];
                b = p2[gi];
            }
            SS(r, c) = a + b;
            SD(r, c) = a - b;
        }
    }
    __syncthreads();

    // ---------- Phase 2: vertical 11-tap conv of s, d, s^2, d^2 ----------
    if (tid < 296) {                 // 74 columns * 4 row-groups of 8
        const int x  = tid % 74;
        const int yb = (tid / 74) * 8;

        float aS[8], aD[8], aP[8], aQ[8];
#pragma unroll
        for (int r = 0; r < 8; ++r) { aS[r] = 0.f; aD[r] = 0.f; aP[r] = 0.f; aQ[r] = 0.f; }
#pragma unroll
        for (int jj = 0; jj < 18; ++jj) {
            const float vs  = SS(yb + jj, x);
            const float vd  = SD(yb + jj, x);
            const float vss = vs * vs;
            const float vdd = vd * vd;
#pragma unroll
            for (int r = 0; r < 8; ++r) {
                const int j = jj - r;
                if (0 <= j && j < 11) {
                    aS[r] = fmaf(GW[j], vs,  aS[r]);
                    aD[r] = fmaf(GW[j], vd,  aD[r]);
                    aP[r] = fmaf(GW[j], vss, aP[r]);
                    aQ[r] = fmaf(GW[j], vdd, aQ[r]);
                }
            }
        }
#pragma unroll
        for (int r = 0; r < 8; ++r) {
            SMID(0, yb + r, x) = aS[r];
            SMID(1, yb + r, x) = aD[r];
            SMID(2, yb + r, x) = aP[r];
            SMID(3, yb + r, x) = aQ[r];
        }
    }
    __syncthreads();

    // ---------- Phase 3: horizontal 11-tap conv + SSIM ----------
    float lsum = 0.f;
    if (tid < 256) {                  // 32 rows * 8 column-groups of 8
        const int y  = tid >> 3;
        const int xb = (tid & 7) * 8;

        float o[4][8];
#pragma unroll
        for (int q = 0; q < 4; ++q) {
            const float4* vp = reinterpret_cast<const float4*>(&SMID(q, y, xb));
            float m[20];
#pragma unroll
            for (int k = 0; k < 5; ++k) {
                const float4 v = vp[k];
                m[4 * k + 0] = v.x;
                m[4 * k + 1] = v.y;
                m[4 * k + 2] = v.z;
                m[4 * k + 3] = v.w;
            }
#pragma unroll
            for (int r = 0; r < 8; ++r) {
                float s = GW[0] * m[r];
#pragma unroll
                for (int i = 1; i < 11; ++i) s = fmaf(GW[i], m[r + i], s);
                o[q][r] = s;
            }
        }
#pragma unroll
        for (int r = 0; r < 8; ++r) {
            const float S = o[0][r], D = o[1][r], P = o[2][r], Q = o[3][r];
            const float S2 = S * S;
            const float D2 = D * D;
            const float t1 = S2 - D2;     // 4*mu1mu2
            const float t2 = S2 + D2;     // 2*(mu1^2+mu2^2)
            const float t5 = (P - Q) - t1;  // 4*sigma12
            const float t6 = (P + Q) - t2;  // 2*(sig1^2+sig2^2)
            const float num = fmaf(0.5f, t1, C1F) * fmaf(0.5f, t5, C2F);
            const float den = fmaf(0.5f, t2, C1F) * fmaf(0.5f, t6, C2F);
            lsum = fmaf(num, fast_rcp(den), lsum);
        }
    }

    // ---------- In-block reduction ----------
#pragma unroll
    for (int off = 16; off > 0; off >>= 1)
        lsum += __shfl_down_sync(0xffffffffu, lsum, off);

    __shared__ float  warp_sums[NTHREADS / 32];
    __shared__ unsigned s_last;
    const int wid  = tid >> 5;
    const int lane = tid & 31;
    if (lane == 0) warp_sums[wid] = lsum;
    __syncthreads();

    // ---------- Fence-free last-block reduction ----------
    if (tid == 0) {
        float s = 0.f;
#pragma unroll
        for (int w = 0; w < NTHREADS / 32; ++w) s += warp_sums[w];
        const int bid = (blockIdx.z * gridDim.y + blockIdx.y) * gridDim.x + blockIdx.x;
        g_part[bid] = s;
        unsigned ticket;
        asm volatile("atom.acq_rel.gpu.global.inc.u32 %0, [%1], %2;"
                     : "=r"(ticket)
                     : "l"(&g_count), "r"(NBLOCKS - 1u)
                     : "memory");
        s_last = (ticket == NBLOCKS - 1u) ? 1u : 0u;
    }
    __syncthreads();

    if (s_last) {
        double d = 0.0;
        for (int i = tid; i < (int)NBLOCKS; i += NTHREADS) d += (double)g_part[i];
#pragma unroll
        for (int off = 16; off > 0; off >>= 1)
            d += __shfl_down_sync(0xffffffffu, d, off);
        __shared__ double wsum[NTHREADS / 32];
        if (lane == 0) wsum[wid] = d;
        __syncthreads();
        if (tid == 0) {
            double t = 0.0;
#pragma unroll
            for (int w = 0; w < NTHREADS / 32; ++w) t += wsum[w];
            out[0] = (float)(t * (1.0 / NPIX));
        }
    }
}

extern "C" void kernel_launch(void* const* d_in, const int* in_sizes, int n_in,
                              void* d_out, int out_size) {
    const float* img1 = (const float*)d_in[0];
    const float* img2 = (const float*)d_in[1];
    float* out = (float*)d_out;

    const int smem_bytes = (2 * SH * SSTR + 4 * TH * SSTR) * (int)sizeof(float); // 64448
    cudaFuncSetAttribute(ssim_main_kernel,
                         cudaFuncAttributeMaxDynamicSharedMemorySize, smem_bytes);

    dim3 grid(HW / TW, HW / TH, PLANES);   // 8 x 16 x 48
    ssim_main_kernel<<<grid, NTHREADS, smem_bytes>>>(img1, img2, out);
}